// round 15
// baseline (speedup 1.0000x reference)
#include <cuda_runtime.h>

// Problem constants
#define BN    4096
#define NFEAT 1024
#define RR    64
#define KK    32
#define DD    16

// Tiling
#define BT      8       // b rows per tile
#define RG      16      // regions per block
#define THREADS 256
#define GRIDX   111     // 111 x 4 groups = 444 blocks = 3 per SM
#define NTILES  (BN / BT)   // 512 b-tiles

#define XPITCH 1028     // smem pitch for raw x rows (bank-decorrelated gather)
#define GPITCH 132      // smem pitch per region for gathered tile [d][b]

#define LOG_2PI_F 1.8378770664093453f

typedef unsigned long long u64;

// Packed fp32x2 helpers (sm_103a FFMA2 — only reachable via PTX)
__device__ __forceinline__ u64 ffma2(u64 a, u64 b, u64 c) {
    u64 d;
    asm("fma.rn.f32x2 %0, %1, %2, %3;" : "=l"(d) : "l"(a), "l"(b), "l"(c));
    return d;
}
__device__ __forceinline__ u64 bcast2(float v) {
    u64 d;
    unsigned int r = __float_as_uint(v);
    asm("mov.b64 %0, {%1, %1};" : "=l"(d) : "r"(r));
    return d;
}
__device__ __forceinline__ void unpack2(u64 v, float& lo, float& hi) {
    unsigned int a, b;
    asm("mov.b64 {%0, %1}, %2;" : "=r"(a), "=r"(b) : "l"(v));
    lo = __uint_as_float(a);
    hi = __uint_as_float(b);
}
__device__ __forceinline__ unsigned int smem_u32(const void* p) {
    unsigned int a;
    asm("{ .reg .u64 t; cvta.to.shared.u64 t, %1; cvt.u32.u64 %0, t; }"
        : "=r"(a) : "l"(p));
    return a;
}

// Precomputed parameters (device globals: no allocation allowed)
__device__ float g_wa[RR * DD * KK];   // [r][d][k] = 1/scale
__device__ float g_wb[RR * DD * KK];   // [r][d][k] = -mean/scale
__device__ float g_c [RR * KK];        // [r][k]
__device__ int   g_idx[RR * DD];       // region indices as int32

// ---------------------------------------------------------------------------
// Prep kernel: 64 blocks (one per region) x 512 threads.
// ---------------------------------------------------------------------------
__global__ void prep_kernel(const float* __restrict__ means,
                            const float* __restrict__ scales,
                            const void*  __restrict__ regions_raw) {
    const int r = blockIdx.x;
    const int t = threadIdx.x;       // 0..511
    const int k = t >> 4;
    const int d = t & 15;

    const float s   = scales[((size_t)r * KK + k) * DD + d];
    const float m   = means [((size_t)r * KK + k) * DD + d];
    const float inv = 1.0f / s;
    g_wa[(r * DD + d) * KK + k] = inv;
    g_wb[(r * DD + d) * KK + k] = -m * inv;

    float lg = logf(s);
#pragma unroll
    for (int o = 8; o >= 1; o >>= 1)
        lg += __shfl_xor_sync(0xffffffffu, lg, o);
    if (d == 0)
        g_c[r * KK + k] = -lg - 0.5f * (float)DD * LOG_2PI_F;

    if (r == 0) {
        // int64 detection: if regions is int64 (values < 1024), every odd
        // 32-bit word is zero.
        __shared__ int s_or;
        if (t == 0) s_or = 0;
        __syncthreads();
        const int* w = (const int*)regions_raw;
        int v = w[2 * t + 1];
#pragma unroll
        for (int o = 16; o >= 1; o >>= 1)
            v |= __shfl_xor_sync(0xffffffffu, v, o);
        if ((t & 31) == 0) atomicOr(&s_or, v);
        __syncthreads();
        const int is64 = (s_or == 0);
        g_idx[2 * t]     = is64 ? w[4 * t]     : w[2 * t];
        g_idx[2 * t + 1] = is64 ? w[4 * t + 2] : w[2 * t + 1];
    }
}

// ---------------------------------------------------------------------------
// Main kernel: persistent blocks, grid = (111, 4) = 444 = 3 blocks/SM.
// Round-14 structure (warp-private gather, ONE barrier/tile, 2-deep ring)
// with weights STREAMED from L1 per d (coalesced float2 LDG; each block's
// 32 KB slice is L1-resident after the first tile) instead of held in 64
// registers -> regs ~70 -> 3 blocks/SM, 24 warps.
// ---------------------------------------------------------------------------
__global__ __launch_bounds__(THREADS, 3)
void main_kernel(const float* __restrict__ x, float* __restrict__ out) {
    extern __shared__ float smem[];
    float* sm_x0  = smem;                         // BT*XPITCH
    float* sm_x1  = smem + BT * XPITCH;           // BT*XPITCH
    float* sm_xg  = smem + 2 * BT * XPITCH;       // RG*GPITCH
    int*   sm_idx = (int*)(sm_xg + RG * GPITCH);  // RG*DD = 256

    const int tid  = threadIdx.x;
    const int r0   = blockIdx.y * RG;
    const int w    = tid >> 5;        // warp: 0..7 owns regions 2w, 2w+1
    const int lane = tid & 31;

    const int rl = tid >> 4;          // consumed region: 0..15
    const int kp = tid & 15;          // k-pair: k0 = kp*2
    const int r  = r0 + rl;
    const int k0 = kp * 2;

    // ---- One-time: gather indices to smem ----
    sm_idx[tid] = g_idx[r0 * DD + tid];           // 256 == RG*DD
    __syncthreads();

    // Hoist this thread's 8 loop-invariant gather columns into registers.
    const int rbase = 2 * w;
    int gcol[8];
#pragma unroll
    for (int i = 0; i < 8; i++) {
        const int e   = lane + 32 * i;
        const int d   = (e >> 3) & (DD - 1);
        const int rgl = e >> 7;
        gcol[i] = sm_idx[(rbase + rgl) * DD + d];
    }

    const float* wap = g_wa + (size_t)r * DD * KK + k0;
    const float* wbp = g_wb + (size_t)r * DD * KK + k0;
    const float2 c2  = *(const float2*)&g_c[r * KK + k0];

    const unsigned int s_x0 = smem_u32(sm_x0);
    const unsigned int s_x1 = smem_u32(sm_x1);
    float* const xg0 = sm_xg + rbase * GPITCH;

    // ---- Prologue: issue load of first tile into buf0 ----
    const int t0 = blockIdx.x;
    {
        const float* xrow = x + (size_t)t0 * BT * NFEAT;
#pragma unroll
        for (int i = tid; i < BT * (NFEAT / 4); i += THREADS) {
            const int row = i >> 8;
            const int c   = i & 255;
            const unsigned int dst = s_x0 + (unsigned)(row * XPITCH + c * 4) * 4u;
            asm volatile("cp.async.cg.shared.global [%0], [%1], 16;"
                         :: "r"(dst), "l"(xrow + (size_t)row * NFEAT + c * 4));
        }
        asm volatile("cp.async.commit_group;" ::: "memory");
    }

    // ---- Pipelined tile loop: ONE block barrier per tile ----
    for (int j = 0, t = t0; t < NTILES; j++, t += GRIDX) {
        asm volatile("cp.async.wait_group 0;" ::: "memory");
        __syncthreads();

        // ---- Warp-local gather of regions 2w, 2w+1 from buf j&1 ----
        const float* sm_cur = (j & 1) ? sm_x1 : sm_x0;
#pragma unroll
        for (int i = 0; i < 8; i++) {
            const int e   = lane + 32 * i;       // 0..255
            const int b   = e & (BT - 1);
            const int d   = (e >> 3) & (DD - 1);
            const int rgl = e >> 7;              // 0 or 1
            xg0[rgl * GPITCH + d * BT + b] = sm_cur[b * XPITCH + gcol[i]];
        }
        __syncwarp();

        // ---- Issue load(j+1) into the other buffer (safe: last reader
        //      gather(j-1) retired at this tile's barrier) ----
        const int tf = t + GRIDX;
        if (tf < NTILES) {
            const unsigned int s_nxt = (j & 1) ? s_x0 : s_x1;
            const float* xrow = x + (size_t)tf * BT * NFEAT;
#pragma unroll
            for (int i = tid; i < BT * (NFEAT / 4); i += THREADS) {
                const int row = i >> 8;
                const int c   = i & 255;
                const unsigned int dst =
                    s_nxt + (unsigned)(row * XPITCH + c * 4) * 4u;
                asm volatile("cp.async.cg.shared.global [%0], [%1], 16;"
                             :: "r"(dst), "l"(xrow + (size_t)row * NFEAT + c * 4));
            }
        }
        asm volatile("cp.async.commit_group;" ::: "memory");

        // ---- Compute (warp-private xg): per d, 2 LDS.128 (broadcast) +
        //      2 LDG.64 (L1-hot weights) + 4 mov + 16 FFMA2 ----
        const float* xp = sm_xg + rl * GPITCH;

        u64 acc0[4], acc1[4];
#pragma unroll
        for (int p = 0; p < 4; p++) { acc0[p] = 0ull; acc1[p] = 0ull; }

#pragma unroll
        for (int d = 0; d < DD; d++) {
            const ulonglong2 xA = *(const ulonglong2*)(xp + d * BT);
            const ulonglong2 xB = *(const ulonglong2*)(xp + d * BT + 4);
            const u64 xv[4] = {xA.x, xA.y, xB.x, xB.y};

            const float2 wa2 = __ldg((const float2*)(wap + d * KK));
            const float2 wb2 = __ldg((const float2*)(wbp + d * KK));
            const u64 aa0 = bcast2(wa2.x);
            const u64 aa1 = bcast2(wa2.y);
            const u64 bb0 = bcast2(wb2.x);
            const u64 bb1 = bcast2(wb2.y);
#pragma unroll
            for (int p = 0; p < 4; p++) {
                const u64 z0 = ffma2(xv[p], aa0, bb0);
                acc0[p] = ffma2(z0, z0, acc0[p]);
                const u64 z1 = ffma2(xv[p], aa1, bb1);
                acc1[p] = ffma2(z1, z1, acc1[p]);
            }
        }

        // ---- Epilogue: out[b][r][k0..k0+1] = -0.5*acc + C ----
        const int b0 = t * BT;
        const u64 nh  = bcast2(-0.5f);
        const u64 cc0 = bcast2(c2.x);
        const u64 cc1 = bcast2(c2.y);
#pragma unroll
        for (int p = 0; p < 4; p++) {
            const u64 o0 = ffma2(acc0[p], nh, cc0);
            const u64 o1 = ffma2(acc1[p], nh, cc1);
            float o0lo, o0hi, o1lo, o1hi;
            unpack2(o0, o0lo, o0hi);
            unpack2(o1, o1lo, o1hi);
            *(float2*)&out[((size_t)(b0 + 2 * p)     * RR + r) * KK + k0] =
                make_float2(o0lo, o1lo);
            *(float2*)&out[((size_t)(b0 + 2 * p + 1) * RR + r) * KK + k0] =
                make_float2(o0hi, o1hi);
        }
    }
}

// ---------------------------------------------------------------------------
#define SMEM_BYTES ((2 * BT * XPITCH + RG * GPITCH) * 4 + RG * DD * 4)

extern "C" void kernel_launch(void* const* d_in, const int* in_sizes, int n_in,
                              void* d_out, int out_size) {
    const float* x       = (const float*)d_in[0];
    const void*  regions = d_in[1];                // int64 or int32, detected
    const float* means   = (const float*)d_in[2];
    const float* scales  = (const float*)d_in[3];
    float*       out     = (float*)d_out;

    cudaFuncSetAttribute(main_kernel,
                         cudaFuncAttributeMaxDynamicSharedMemorySize,
                         SMEM_BYTES);

    prep_kernel<<<RR, 512>>>(means, scales, regions);

    dim3 grid(GRIDX, RR / RG);
    main_kernel<<<grid, THREADS, SMEM_BYTES>>>(x, out);
}